// round 7
// baseline (speedup 1.0000x reference)
#include <cuda_runtime.h>
#include <cuda_fp16.h>

#define D        64
#define N_MAX    100000
#define E_MAX    800000
#define NC_NODES 500
#define EC_MAX   20000
#define HP       6
#define SCAN_BLK 1024
#define NBLK_MAX ((N_MAX + SCAN_BLK - 1) / SCAN_BLK)
#define REC      24

// Static scratch
__device__ __half g_nhalf[N_MAX * D];     // fp16 rows
__device__ float  g_rec[N_MAX * REC];     // per-node dots: [0..6]=h·n_f, [8..14]=h·r_f, [16..21]=h·trel_h, [22]=||h||²
__device__ float  g_wslot[E_MAX];
__device__ int    g_slot_src[E_MAX];
__device__ float  g_cw[EC_MAX];
__device__ float  g_cdenom[NC_NODES];
__device__ float  g_trel[HP * D];
__device__ float  g_snr[8];               // norm_f · rel_f
__device__ float  g_stt[8];               // norm_5 · trel_h
__device__ int    g_cnt[N_MAX];           // ==0 at entry (static init; k34 resets)
__device__ int    g_off[N_MAX];
__device__ int    g_bsum[NBLK_MAX];
__device__ int    g_start[N_MAX + 1];
__device__ int    g_cursor[N_MAX];

// ---------------------------------------------------------------------------
__device__ __forceinline__ float sum8(float v) {
    #pragma unroll
    for (int o = 4; o > 0; o >>= 1) v += __shfl_xor_sync(0xffffffffu, v, o);
    return v;
}
__device__ __forceinline__ float warp_sum(float v) {
    #pragma unroll
    for (int o = 16; o > 0; o >>= 1) v += __shfl_xor_sync(0xffffffffu, v, o);
    return v;
}
__device__ __forceinline__ void red_add_v4(float* p, float x, float y, float z, float w) {
    asm volatile("red.global.add.v4.f32 [%0], {%1,%2,%3,%4};"
                 :: "l"(p), "f"(x), "f"(y), "f"(z), "f"(w) : "memory");
}
__device__ __forceinline__ void unpack8(float4 v, float* o) {
    const __half2* p = (const __half2*)&v;
    float2 f0 = __half22float2(p[0]);
    float2 f1 = __half22float2(p[1]);
    float2 f2 = __half22float2(p[2]);
    float2 f3 = __half22float2(p[3]);
    o[0] = f0.x; o[1] = f0.y; o[2] = f1.x; o[3] = f1.y;
    o[4] = f2.x; o[5] = f2.y; o[6] = f3.x; o[7] = f3.y;
}

// ---------------------------------------------------------------------------
// K_pre: time_rel (6 vectors) + snr/stt constants. One block, 384 threads.
__global__ void k_pre(const float* __restrict__ hour_emb,
                      const float* __restrict__ W,
                      const float* __restrict__ b,
                      const float* __restrict__ norm_emb,
                      const float* __restrict__ rel_emb) {
    __shared__ float mix[HP][D];
    __shared__ float red[HP][D];
    __shared__ float trel_s[HP][D];
    int tid = threadIdx.x;          // 0..383
    int h = tid >> 6, j = tid & 63; // h in 0..5
    {
        int lh = (h - 1 + HP) % HP, nh = (h + 1) % HP;
        mix[h][j] = (hour_emb[lh * D + j] + hour_emb[h * D + j] + hour_emb[nh * D + j]) * (1.f / 3.f);
    }
    __syncthreads();
    float o = b[j];
    #pragma unroll
    for (int k = 0; k < D; k++) o = fmaf(W[j * D + k], mix[h][k], o);
    red[h][j] = o * o;
    __syncthreads();
    #pragma unroll
    for (int s = 32; s > 0; s >>= 1) {
        if (j < s) red[h][j] += red[h][j + s];
        __syncthreads();
    }
    float t = o / fmaxf(sqrtf(red[h][0]), 1e-12f);
    trel_s[h][j] = t;
    g_trel[h * D + j] = t;
    __syncthreads();
    if (tid < 7) {
        float s = 0.f;
        #pragma unroll
        for (int q = 0; q < D; q++) s = fmaf(norm_emb[tid * D + q], rel_emb[tid * D + q], s);
        g_snr[tid] = s;
    } else if (tid >= 8 && tid < 8 + HP) {
        int hh = tid - 8;
        float s = 0.f;
        #pragma unroll
        for (int q = 0; q < D; q++) s = fmaf(norm_emb[5 * D + q], trel_s[hh][q], s);
        g_stt[hh] = s;
    }
}

// ---------------------------------------------------------------------------
// K0: fp16 convert + per-node dot records + dst histogram + zero cat_hid/cdenom.
// Block handles 16 nodes; 128 threads.
__global__ void __launch_bounds__(128) k0_init(
        const float* __restrict__ nfeat, int NN,
        const int* __restrict__ dst, int E,
        const float* __restrict__ norm_emb,
        const float* __restrict__ rel_emb,
        float* __restrict__ cat_hid) {
    __shared__ __align__(16) float tab[20 * D];   // 0-6 norm, 7-13 rel, 14-19 trel
    __shared__ __align__(16) float rows[16 * D];
    int tid = threadIdx.x;
    int blk = blockIdx.x;

    for (int i = tid; i < 7 * D; i += 128) tab[i] = norm_emb[i];
    for (int i = tid; i < 7 * D; i += 128) tab[7 * D + i] = rel_emb[i];
    for (int i = tid; i < 6 * D; i += 128) tab[14 * D + i] = g_trel[i];

    int node0 = blk * 16;
    for (int i = tid; i < 16 * D; i += 128) {
        int node = node0 + i / D;
        float x = (node < NN) ? nfeat[node0 * D + i] : 0.f;
        __half hx = __float2half_rn(x);
        if (node < NN) g_nhalf[node0 * D + i] = hx;
        rows[i] = __half2float(hx);
    }
    __syncthreads();

    int nl = tid >> 3;        // 0..15
    int slot = tid & 7;       // 0..7
    int node = node0 + nl;
    if (node < NN) {
        const float4* row4 = (const float4*)(rows + nl * D);
        #pragma unroll
        for (int k = 0; k < 3; k++) {
            int idx = slot + 8 * k;
            if (idx > 20) continue;
            const float4* v4 = (idx == 20) ? row4 : (const float4*)(tab + idx * D);
            float acc = 0.f;
            #pragma unroll
            for (int q = 0; q < 16; q++) {
                float4 a = row4[q];
                float4 c = v4[q];
                acc = fmaf(a.x, c.x, fmaf(a.y, c.y, fmaf(a.z, c.z, fmaf(a.w, c.w, acc))));
            }
            int recidx = (idx < 7) ? idx : (idx < 14) ? idx + 1 : (idx < 20) ? idx + 2 : 22;
            g_rec[node * REC + recidx] = acc;
        }
    }

    // histogram + zeros (grid-stride)
    int gtid = blk * 128 + tid;
    int gstride = gridDim.x * 128;
    for (int e = gtid; e < E; e += gstride) atomicAdd(&g_cnt[dst[e]], 1);
    for (int i = gtid; i < NC_NODES * D; i += gstride) cat_hid[i] = 0.f;
    for (int i = gtid; i < NC_NODES; i += gstride) g_cdenom[i] = 0.f;
}

// ---------------------------------------------------------------------------
// K2: per-block scan of g_cnt (1024 elements/block)
__global__ void k2_scan_blocks(int NN) {
    __shared__ int sh[256];
    int b = blockIdx.x, t = threadIdx.x;
    int base = b * SCAN_BLK + t * 4;
    int v0 = (base + 0 < NN) ? g_cnt[base + 0] : 0;
    int v1 = (base + 1 < NN) ? g_cnt[base + 1] : 0;
    int v2 = (base + 2 < NN) ? g_cnt[base + 2] : 0;
    int v3 = (base + 3 < NN) ? g_cnt[base + 3] : 0;
    int s = v0 + v1 + v2 + v3;
    sh[t] = s;
    __syncthreads();
    #pragma unroll
    for (int off = 1; off < 256; off <<= 1) {
        int x = (t >= off) ? sh[t - off] : 0;
        __syncthreads();
        sh[t] += x;
        __syncthreads();
    }
    if (t == 255) g_bsum[b] = sh[255];
    int run = sh[t] - s;
    if (base + 0 < NN) g_off[base + 0] = run; run += v0;
    if (base + 1 < NN) g_off[base + 1] = run; run += v1;
    if (base + 2 < NN) g_off[base + 2] = run; run += v2;
    if (base + 3 < NN) g_off[base + 3] = run;
}

// K34: merged block-sum scan + finalize (+ g_cnt reset for next replay)
__global__ void k34_finalize(int NN, int E, int nblk) {
    __shared__ int sh[128];
    int t = threadIdx.x;   // 512
    if (t < 128) sh[t] = (t < nblk) ? g_bsum[t] : 0;
    __syncthreads();
    #pragma unroll
    for (int off = 1; off < 128; off <<= 1) {
        int x = (t >= off && t < 128) ? sh[t - off] : 0;
        __syncthreads();
        if (t < 128) sh[t] += x;
        __syncthreads();
    }
    int sb = (blockIdx.x * 512) >> 10;
    int bpre = (sb > 0) ? sh[sb - 1] : 0;
    int i = blockIdx.x * 512 + t;
    if (i < NN) {
        int v = g_off[i] + bpre;
        g_start[i] = v;
        g_cursor[i] = v;
        g_cnt[i] = 0;
    }
    if (i == 0) g_start[NN] = E;
}

// ---------------------------------------------------------------------------
// K6: pass-1 scores via algebraic expansion; 8 lanes/edge, 4 edges/warp,
//     fused CSR scatter. Low warps handle category edges.
__global__ void __launch_bounds__(256) k6_pass1(
        const float* __restrict__ cat_emb,
        const float* __restrict__ rel_emb,
        const int* __restrict__ src,
        const int* __restrict__ dst,
        const int* __restrict__ ftype,
        const int* __restrict__ hourid,
        const int* __restrict__ csrc,
        const int* __restrict__ cdst,
        int E, int EC, int warps_cat, int n_warps) {
    int w = (blockIdx.x * blockDim.x + threadIdx.x) >> 5;
    int lane = threadIdx.x & 31;
    if (w >= n_warps) return;
    int grp = lane >> 3;
    int l   = lane & 7;

    if (w < warps_cat) {
        int e = 4 * w + grp;
        bool valid = (e < EC);
        int ec = valid ? e : EC - 1;
        int s = csrc[ec], d = cdst[ec];
        const float4* ce4 = (const float4*)cat_emb;
        const float4* re4 = (const float4*)rel_emb;
        float ssq = 0.f;
        #pragma unroll
        for (int q = 0; q < 2; q++) {
            float4 hc = ce4[s * 16 + 2 * l + q];
            float4 tc = ce4[d * 16 + 2 * l + q];
            float4 rc = re4[6 * 16 + 2 * l + q];
            float dx = hc.x + rc.x - tc.x;
            float dy = hc.y + rc.y - tc.y;
            float dz = hc.z + rc.z - tc.z;
            float dw = hc.w + rc.w - tc.w;
            ssq += fmaf(dx, dx, fmaf(dy, dy, fmaf(dz, dz, dw * dw)));
        }
        ssq = sum8(ssq);
        if (l == 0 && valid) {
            float wgt = __expf(__expf(-ssq));
            g_cw[e] = wgt;
            atomicAdd(&g_cdenom[d], wgt);
        }
    } else {
        int e = 4 * (w - warps_cat) + grp;
        bool valid = (e < E);
        int ec = valid ? e : E - 1;
        int s = src[ec], d = dst[ec], f = ftype[ec], h = hourid[ec];

        const float4* nh4 = (const float4*)g_nhalf;   // 8 float4 per row
        float a[8], bb[8];
        unpack8(nh4[s * 8 + l], a);
        unpack8(nh4[d * 8 + l], bb);
        float ht = 0.f;
        #pragma unroll
        for (int i = 0; i < 8; i++) ht = fmaf(a[i], bb[i], ht);

        const float* rs = g_rec + s * REC;
        const float* rd = g_rec + d * REC;
        float hn_s = 0.f, hn_d = 0.f, hn5_s = 0.f, hn5_d = 0.f, snr = 0.f, stt = 0.f;
        float extra = 0.f;
        if (l == 0) {
            extra = 2.f * rs[22];
            hn_s = rs[f];  hn_d = rd[f];
            hn5_s = rs[5]; hn5_d = rd[5];
            snr = g_snr[f]; stt = g_stt[h];
        } else if (l == 1) extra =  2.f * rd[22];
        else   if (l == 2) extra =  2.f * rs[8 + f];
        else   if (l == 3) extra = -2.f * rd[8 + f];
        else   if (l == 4) extra =  2.f * rs[16 + h];
        else   if (l == 5) extra = -2.f * rd[16 + h];
        else   if (l == 6) extra =  2.f;

        float T = sum8(fmaf(-4.f, ht, extra));

        if (l == 0 && valid) {
            float dot1 = hn_s - hn_d;
            float dot2 = hn5_s - hn5_d;
            float ssq = T - dot1 * dot1 - dot2 * dot2
                          - 2.f * dot1 * snr - 2.f * dot2 * stt;
            float wgt = __expf(__expf(-ssq));
            int pos = atomicAdd(&g_cursor[d], 1);
            g_slot_src[pos] = s;
            g_wslot[pos] = wgt;
        }
    }
}

// ---------------------------------------------------------------------------
// K7: low warps = cat REDG; others = 1 node per warp CSR gather with
//     shuffle-broadcast (weight, src) chunks.
__global__ void k7_aggregate(const float* __restrict__ cat_emb,
                             const int* __restrict__ csrc,
                             const int* __restrict__ cdst,
                             float* __restrict__ rst,
                             float* __restrict__ cat_hid,
                             int NN, int EC, int ECH, int n_warps) {
    int w = (blockIdx.x * blockDim.x + threadIdx.x) >> 5;
    int lane = threadIdx.x & 31;
    if (w >= n_warps) return;

    if (w < ECH) {
        int half = lane >> 4, l = lane & 15;
        int e = 2 * w + half;
        if (e >= EC) return;
        int s = csrc[e], d = cdst[e];
        float coeff = g_cw[e] / g_cdenom[d];
        float4 v = ((const float4*)cat_emb)[s * 16 + l];
        red_add_v4(&cat_hid[d * D + l * 4],
                   v.x * coeff, v.y * coeff, v.z * coeff, v.w * coeff);
    } else {
        int node = w - ECH;
        if (node >= NN) return;
        int st = g_start[node], en = g_start[node + 1];
        float2 acc = make_float2(0.f, 0.f);
        if (en > st) {
            float denom = 0.f;
            for (int j = st + lane; j < en; j += 32) denom += g_wslot[j];
            denom = warp_sum(denom);
            float inv = 1.f / denom;
            const __half2* nh2 = (const __half2*)g_nhalf;  // 32 half2 per row
            for (int base = st; base < en; base += 32) {
                int m = min(32, en - base);
                float wv = 0.f; int sv = 0;
                if (lane < m) { wv = g_wslot[base + lane]; sv = g_slot_src[base + lane]; }
                for (int k = 0; k < m; k++) {
                    float cw = __shfl_sync(0xffffffffu, wv, k) * inv;
                    int s    = __shfl_sync(0xffffffffu, sv, k);
                    float2 v = __half22float2(nh2[s * 32 + lane]);
                    acc.x = fmaf(cw, v.x, acc.x);
                    acc.y = fmaf(cw, v.y, acc.y);
                }
            }
        }
        ((float2*)rst)[node * 32 + lane] = acc;
    }
}

// ---------------------------------------------------------------------------
extern "C" void kernel_launch(void* const* d_in, const int* in_sizes, int n_in,
                              void* d_out, int out_size) {
    const float* nfeat      = (const float*)d_in[0];
    const float* cat_emb    = (const float*)d_in[1];
    const float* rel_emb    = (const float*)d_in[2];
    const float* norm_emb   = (const float*)d_in[3];
    const float* hour_emb   = (const float*)d_in[4];
    const float* time_rel_w = (const float*)d_in[5];
    const float* time_rel_b = (const float*)d_in[6];
    const int*   src        = (const int*)d_in[7];
    const int*   dst        = (const int*)d_in[8];
    const int*   ftype      = (const int*)d_in[9];
    const int*   hourid     = (const int*)d_in[10];
    const int*   cat_src    = (const int*)d_in[11];
    const int*   cat_dst    = (const int*)d_in[12];

    const int NN = in_sizes[0] / D;
    const int E  = in_sizes[7];
    const int EC = in_sizes[11];

    float* out     = (float*)d_out;
    float* rst     = out;
    float* cat_hid = out + NN * D;

    // constants: time_rel + snr/stt
    k_pre<<<1, 384>>>(hour_emb, time_rel_w, time_rel_b, norm_emb, rel_emb);

    // convert + per-node dots + histogram + zeros
    k0_init<<<(NN + 15) / 16, 128>>>(nfeat, NN, dst, E, norm_emb, rel_emb, cat_hid);

    // CSR row pointers
    int nblk = (NN + SCAN_BLK - 1) / SCAN_BLK;
    k2_scan_blocks<<<nblk, 256>>>(NN);
    k34_finalize<<<(NN + 511) / 512, 512>>>(NN, E, nblk);

    // Pass 1 (scores + fused scatter)
    {
        int warps_cat = (EC + 3) / 4;
        int n_warps = warps_cat + (E + 3) / 4;
        int blocks = (n_warps * 32 + 255) / 256;
        k6_pass1<<<blocks, 256>>>(cat_emb, rel_emb,
                                  src, dst, ftype, hourid, cat_src, cat_dst,
                                  E, EC, warps_cat, n_warps);
    }

    // Pass 2 (aggregate)
    {
        int ECH = (EC + 1) / 2;
        int n_warps = ECH + NN;
        int blocks = (n_warps * 32 + 255) / 256;
        k7_aggregate<<<blocks, 256>>>(cat_emb, cat_src, cat_dst,
                                      rst, cat_hid, NN, EC, ECH, n_warps);
    }
}

// round 8
// speedup vs baseline: 2.1918x; 2.1918x over previous
#include <cuda_runtime.h>
#include <cuda_fp16.h>

#define D        64
#define N_MAX    100000
#define E_MAX    800000
#define NC_NODES 500
#define EC_MAX   20000
#define HP       6
#define SCAN_BLK 1024
#define NBLK_MAX ((N_MAX + SCAN_BLK - 1) / SCAN_BLK)

// Static scratch
__device__ __half g_nhalf[N_MAX * D];   // fp16 copy of nfeat
__device__ float  g_wslot[E_MAX];       // softmax weight per CSR slot
__device__ float  g_cw[EC_MAX];
__device__ float  g_cdenom[NC_NODES];
__device__ float  g_trel[HP * D];
__device__ int    g_cnt[N_MAX];         // ==0 at entry (static init; k34 resets each call)
__device__ int    g_off[N_MAX];
__device__ int    g_bsum[NBLK_MAX];
__device__ int    g_start[N_MAX + 1];
__device__ int    g_cursor[N_MAX];
__device__ int    g_slot_src[E_MAX];

// ---------------------------------------------------------------------------
__device__ __forceinline__ float sum8(float v) {
    #pragma unroll
    for (int o = 4; o > 0; o >>= 1) v += __shfl_xor_sync(0xffffffffu, v, o);
    return v;
}
__device__ __forceinline__ float half_sum(float v) {
    #pragma unroll
    for (int o = 8; o > 0; o >>= 1) v += __shfl_xor_sync(0xffffffffu, v, o);
    return v;
}
__device__ __forceinline__ void red_add_v4(float* p, float x, float y, float z, float w) {
    asm volatile("red.global.add.v4.f32 [%0], {%1,%2,%3,%4};"
                 :: "l"(p), "f"(x), "f"(y), "f"(z), "f"(w) : "memory");
}
// unpack a float4 holding 8 halfs into 8 floats
__device__ __forceinline__ void unpack8(float4 v, float* o) {
    const __half2* p = (const __half2*)&v;
    float2 f0 = __half22float2(p[0]);
    float2 f1 = __half22float2(p[1]);
    float2 f2 = __half22float2(p[2]);
    float2 f3 = __half22float2(p[3]);
    o[0] = f0.x; o[1] = f0.y; o[2] = f1.x; o[3] = f1.y;
    o[4] = f2.x; o[5] = f2.y; o[6] = f3.x; o[7] = f3.y;
}

// ---------------------------------------------------------------------------
// K0: fp16 convert + dst histogram + zero cat_hid/cdenom + time_rel (blocks 0..5)
__global__ void k0_init(const float* __restrict__ nfeat, int NN,
                        const int* __restrict__ dst, int E,
                        float* __restrict__ cat_hid,
                        const float* __restrict__ hour_emb,
                        const float* __restrict__ W,
                        const float* __restrict__ b) {
    int stride = gridDim.x * blockDim.x;
    int tid = blockIdx.x * blockDim.x + threadIdx.x;

    const float2* nf2 = (const float2*)nfeat;
    __half2* nh2 = (__half2*)g_nhalf;
    int n2 = NN * D / 2;
    for (int i = tid; i < n2; i += stride)
        nh2[i] = __float22half2_rn(nf2[i]);
    for (int e = tid; e < E; e += stride)
        atomicAdd(&g_cnt[dst[e]], 1);
    for (int i = tid; i < NC_NODES * D; i += stride)
        cat_hid[i] = 0.f;
    for (int i = tid; i < NC_NODES; i += stride)
        g_cdenom[i] = 0.f;

    if (blockIdx.x < HP) {
        __shared__ float mix[D];
        __shared__ float red[D];
        int h = blockIdx.x;
        int j = threadIdx.x;
        if (j < D) {
            int lh = (h - 1 + HP) % HP, nh = (h + 1) % HP;
            mix[j] = (hour_emb[lh * D + j] + hour_emb[h * D + j] + hour_emb[nh * D + j]) * (1.f / 3.f);
        }
        __syncthreads();
        float o = 0.f;
        if (j < D) {
            o = b[j];
            #pragma unroll
            for (int k = 0; k < D; k++) o = fmaf(W[j * D + k], mix[k], o);
            red[j] = o * o;
        }
        __syncthreads();
        #pragma unroll
        for (int s = 32; s > 0; s >>= 1) {
            if (j < s) red[j] += red[j + s];
            __syncthreads();
        }
        if (j < D) g_trel[h * D + j] = o / fmaxf(sqrtf(red[0]), 1e-12f);
    }
}

// K2: per-block scan (1024 elements/block, 256 threads x 4)
__global__ void k2_scan_blocks(int NN) {
    __shared__ int sh[256];
    int b = blockIdx.x, t = threadIdx.x;
    int base = b * SCAN_BLK + t * 4;
    int v0 = (base + 0 < NN) ? g_cnt[base + 0] : 0;
    int v1 = (base + 1 < NN) ? g_cnt[base + 1] : 0;
    int v2 = (base + 2 < NN) ? g_cnt[base + 2] : 0;
    int v3 = (base + 3 < NN) ? g_cnt[base + 3] : 0;
    int s = v0 + v1 + v2 + v3;
    sh[t] = s;
    __syncthreads();
    #pragma unroll
    for (int off = 1; off < 256; off <<= 1) {
        int x = (t >= off) ? sh[t - off] : 0;
        __syncthreads();
        sh[t] += x;
        __syncthreads();
    }
    if (t == 255) g_bsum[b] = sh[255];
    int run = sh[t] - s;
    if (base + 0 < NN) g_off[base + 0] = run; run += v0;
    if (base + 1 < NN) g_off[base + 1] = run; run += v1;
    if (base + 2 < NN) g_off[base + 2] = run; run += v2;
    if (base + 3 < NN) g_off[base + 3] = run;
}

// K34: merged block-sum scan + finalize (+ g_cnt reset for next replay)
__global__ void k34_finalize(int NN, int E, int nblk) {
    __shared__ int sh[128];
    int t = threadIdx.x;   // 512
    if (t < 128) sh[t] = (t < nblk) ? g_bsum[t] : 0;
    __syncthreads();
    #pragma unroll
    for (int off = 1; off < 128; off <<= 1) {
        int x = (t >= off && t < 128) ? sh[t - off] : 0;
        __syncthreads();
        if (t < 128) sh[t] += x;
        __syncthreads();
    }
    int sb = (blockIdx.x * 512) >> 10;
    int bpre = (sb > 0) ? sh[sb - 1] : 0;
    int i = blockIdx.x * 512 + t;
    if (i < NN) {
        int v = g_off[i] + bpre;
        g_start[i] = v;
        g_cursor[i] = v;
        g_cnt[i] = 0;
    }
    if (i == 0) g_start[NN] = E;
}

// ---------------------------------------------------------------------------
// K6: pass-1 scores, 8 lanes per edge, 4 edges per warp, fused CSR scatter.
//   warp w < warps_cat : 4 category edges
//   warp w >= warps_cat: 4 main edges
__global__ void __launch_bounds__(256) k6_pass1(
        const float* __restrict__ cat_emb,
        const float* __restrict__ rel_emb,
        const float* __restrict__ norm_emb,
        const int* __restrict__ src,
        const int* __restrict__ dst,
        const int* __restrict__ ftype,
        const int* __restrict__ hourid,
        const int* __restrict__ csrc,
        const int* __restrict__ cdst,
        int E, int EC, int warps_cat, int n_warps) {
    int w = (blockIdx.x * blockDim.x + threadIdx.x) >> 5;
    int lane = threadIdx.x & 31;
    if (w >= n_warps) return;
    int grp = lane >> 3;       // 0..3
    int l   = lane & 7;        // 0..7

    if (w < warps_cat) {
        int e = 4 * w + grp;
        bool valid = (e < EC);
        int ec = valid ? e : EC - 1;
        int s = csrc[ec], d = cdst[ec];
        const float4* ce4 = (const float4*)cat_emb;
        const float4* re4 = (const float4*)rel_emb;
        float ssq = 0.f;
        #pragma unroll
        for (int q = 0; q < 2; q++) {
            float4 hc = ce4[s * 16 + 2 * l + q];
            float4 tc = ce4[d * 16 + 2 * l + q];
            float4 rc = re4[6 * 16 + 2 * l + q];
            float dx = hc.x + rc.x - tc.x;
            float dy = hc.y + rc.y - tc.y;
            float dz = hc.z + rc.z - tc.z;
            float dw = hc.w + rc.w - tc.w;
            ssq += fmaf(dx, dx, fmaf(dy, dy, fmaf(dz, dz, dw * dw)));
        }
        ssq = sum8(ssq);
        if (l == 0 && valid) {
            float wgt = __expf(__expf(-ssq));
            g_cw[e] = wgt;
            atomicAdd(&g_cdenom[d], wgt);
        }
    } else {
        int e = 4 * (w - warps_cat) + grp;
        bool valid = (e < E);
        int ec = valid ? e : E - 1;
        int s = src[ec], d = dst[ec], f = ftype[ec], h = hourid[ec];

        const float4* nh4 = (const float4*)g_nhalf;   // 8 halfs per float4, 8 float4/row
        float a[8], bb[8], u[8];
        unpack8(nh4[s * 8 + l], a);
        unpack8(nh4[d * 8 + l], bb);
        #pragma unroll
        for (int i = 0; i < 8; i++) u[i] = a[i] - bb[i];

        const float4* nm4 = (const float4*)norm_emb;  // 16 float4 per row
        const float4* re4 = (const float4*)rel_emb;
        const float4* tr4 = (const float4*)g_trel;

        float4 n0  = nm4[f * 16 + 2 * l],  n1  = nm4[f * 16 + 2 * l + 1];
        float4 tn0 = nm4[5 * 16 + 2 * l],  tn1 = nm4[5 * 16 + 2 * l + 1];
        float n[8]  = {n0.x, n0.y, n0.z, n0.w, n1.x, n1.y, n1.z, n1.w};
        float tn[8] = {tn0.x, tn0.y, tn0.z, tn0.w, tn1.x, tn1.y, tn1.z, tn1.w};

        float p1 = 0.f, p2 = 0.f;
        #pragma unroll
        for (int i = 0; i < 8; i++) {
            p1 = fmaf(u[i], n[i], p1);
            p2 = fmaf(u[i], tn[i], p2);
        }
        float dot1 = sum8(p1);
        float dot2 = sum8(p2);

        float4 r0  = re4[f * 16 + 2 * l],  r1  = re4[f * 16 + 2 * l + 1];
        float4 t0  = tr4[h * 16 + 2 * l],  t1  = tr4[h * 16 + 2 * l + 1];
        float r[8]  = {r0.x, r0.y, r0.z, r0.w, r1.x, r1.y, r1.z, r1.w};
        float tr[8] = {t0.x, t0.y, t0.z, t0.w, t1.x, t1.y, t1.z, t1.w};

        float ssq = 0.f;
        #pragma unroll
        for (int i = 0; i < 8; i++) {
            float d1 = u[i] - dot1 * n[i] + r[i];
            float d2 = u[i] - dot2 * tn[i] + tr[i];
            ssq = fmaf(d1, d1, fmaf(d2, d2, ssq));
        }
        ssq = sum8(ssq);

        if (l == 0 && valid) {
            float wgt = __expf(__expf(-ssq));
            int pos = atomicAdd(&g_cursor[d], 1);
            g_slot_src[pos] = s;
            g_wslot[pos] = wgt;
        }
    }
}

// ---------------------------------------------------------------------------
// K7: warps < ECH: cat pass2 (REDG into zeroed cat_hid). Others: 2 nodes/warp gather.
__global__ void k7_aggregate(const float* __restrict__ cat_emb,
                             const int* __restrict__ csrc,
                             const int* __restrict__ cdst,
                             float* __restrict__ rst,
                             float* __restrict__ cat_hid,
                             int NN, int EC, int ECH, int n_warps) {
    int w = (blockIdx.x * blockDim.x + threadIdx.x) >> 5;
    int lane = threadIdx.x & 31;
    if (w >= n_warps) return;
    int half = lane >> 4;
    int l = lane & 15;

    if (w < ECH) {
        int e = 2 * w + half;
        if (e >= EC) return;
        int s = csrc[e], d = cdst[e];
        float coeff = g_cw[e] / g_cdenom[d];
        float4 v = ((const float4*)cat_emb)[s * 16 + l];
        red_add_v4(&cat_hid[d * D + l * 4],
                   v.x * coeff, v.y * coeff, v.z * coeff, v.w * coeff);
    } else {
        int node = 2 * (w - ECH) + half;
        if (node >= NN) return;
        int st = g_start[node], en = g_start[node + 1];
        float4 acc = make_float4(0.f, 0.f, 0.f, 0.f);
        if (en > st) {
            float denom = 0.f;
            for (int j = st + l; j < en; j += 16) denom += g_wslot[j];
            denom = half_sum(denom);
            float inv = 1.f / denom;
            const float2* nh2 = (const float2*)g_nhalf;
            for (int j = st; j < en; j++) {
                float cw = g_wslot[j] * inv;
                int s = g_slot_src[j];
                float2 rv = nh2[s * 16 + l];
                __half2* pv = (__half2*)&rv;
                float2 v0 = __half22float2(pv[0]), v1 = __half22float2(pv[1]);
                acc.x = fmaf(cw, v0.x, acc.x);
                acc.y = fmaf(cw, v0.y, acc.y);
                acc.z = fmaf(cw, v1.x, acc.z);
                acc.w = fmaf(cw, v1.y, acc.w);
            }
        }
        ((float4*)rst)[node * 16 + l] = acc;
    }
}

// ---------------------------------------------------------------------------
extern "C" void kernel_launch(void* const* d_in, const int* in_sizes, int n_in,
                              void* d_out, int out_size) {
    const float* nfeat      = (const float*)d_in[0];
    const float* cat_emb    = (const float*)d_in[1];
    const float* rel_emb    = (const float*)d_in[2];
    const float* norm_emb   = (const float*)d_in[3];
    const float* hour_emb   = (const float*)d_in[4];
    const float* time_rel_w = (const float*)d_in[5];
    const float* time_rel_b = (const float*)d_in[6];
    const int*   src        = (const int*)d_in[7];
    const int*   dst        = (const int*)d_in[8];
    const int*   ftype      = (const int*)d_in[9];
    const int*   hourid     = (const int*)d_in[10];
    const int*   cat_src    = (const int*)d_in[11];
    const int*   cat_dst    = (const int*)d_in[12];

    const int NN = in_sizes[0] / D;
    const int E  = in_sizes[7];
    const int EC = in_sizes[11];

    float* out     = (float*)d_out;
    float* rst     = out;
    float* cat_hid = out + NN * D;

    // K0: convert + histogram + zeros + time_rel
    k0_init<<<2048, 256>>>(nfeat, NN, dst, E, cat_hid, hour_emb, time_rel_w, time_rel_b);

    // CSR row pointers (scatter fused into pass1)
    int nblk = (NN + SCAN_BLK - 1) / SCAN_BLK;
    k2_scan_blocks<<<nblk, 256>>>(NN);
    k34_finalize<<<(NN + 511) / 512, 512>>>(NN, E, nblk);

    // Pass 1 (scores + fused scatter)
    {
        int warps_cat = (EC + 3) / 4;
        int n_warps = warps_cat + (E + 3) / 4;
        int blocks = (n_warps * 32 + 255) / 256;
        k6_pass1<<<blocks, 256>>>(cat_emb, rel_emb, norm_emb,
                                  src, dst, ftype, hourid, cat_src, cat_dst,
                                  E, EC, warps_cat, n_warps);
    }

    // Pass 2 (aggregate)
    {
        int ECH = (EC + 1) / 2;
        int n_warps = ECH + (NN + 1) / 2;
        int blocks = (n_warps * 32 + 255) / 256;
        k7_aggregate<<<blocks, 256>>>(cat_emb, cat_src, cat_dst,
                                      rst, cat_hid, NN, EC, ECH, n_warps);
    }
}

// round 9
// speedup vs baseline: 2.2738x; 1.0374x over previous
#include <cuda_runtime.h>
#include <cuda_fp16.h>

#define D        64
#define N_MAX    100000
#define E_MAX    800000
#define NC_NODES 500
#define EC_MAX   20000
#define HP       6
#define SCAN_BLK 1024
#define NBLK_MAX ((N_MAX + SCAN_BLK - 1) / SCAN_BLK)

// Static scratch
__device__ __half g_nhalf[N_MAX * D];   // fp16 copy of nfeat
__device__ __half g_ntab[7 * D];        // fp16 norm_emb
__device__ __half g_rtab[7 * D];        // fp16 rel_emb
__device__ __half g_ttab[HP * D];       // fp16 time_rel
__device__ float  g_wslot[E_MAX];       // softmax weight per CSR slot
__device__ float  g_cw[EC_MAX];
__device__ float  g_cdenom[NC_NODES];
__device__ int    g_cnt[N_MAX];         // ==0 at entry (static init; k34 resets each call)
__device__ int    g_off[N_MAX];
__device__ int    g_bsum[NBLK_MAX];
__device__ int    g_start[N_MAX + 1];
__device__ int    g_cursor[N_MAX];
__device__ int    g_slot_src[E_MAX];

// ---------------------------------------------------------------------------
__device__ __forceinline__ float sum8(float v) {
    #pragma unroll
    for (int o = 4; o > 0; o >>= 1) v += __shfl_xor_sync(0xffffffffu, v, o);
    return v;
}
__device__ __forceinline__ float half_sum(float v) {
    #pragma unroll
    for (int o = 8; o > 0; o >>= 1) v += __shfl_xor_sync(0xffffffffu, v, o);
    return v;
}
__device__ __forceinline__ void red_add_v4(float* p, float x, float y, float z, float w) {
    asm volatile("red.global.add.v4.f32 [%0], {%1,%2,%3,%4};"
                 :: "l"(p), "f"(x), "f"(y), "f"(z), "f"(w) : "memory");
}
// unpack a float4 holding 8 halfs into 8 floats
__device__ __forceinline__ void unpack8(float4 v, float* o) {
    const __half2* p = (const __half2*)&v;
    float2 f0 = __half22float2(p[0]);
    float2 f1 = __half22float2(p[1]);
    float2 f2 = __half22float2(p[2]);
    float2 f3 = __half22float2(p[3]);
    o[0] = f0.x; o[1] = f0.y; o[2] = f1.x; o[3] = f1.y;
    o[4] = f2.x; o[5] = f2.y; o[6] = f3.x; o[7] = f3.y;
}

// ---------------------------------------------------------------------------
// K0: fp16 conversions (nfeat + tables) + dst histogram + zero cat_hid/cdenom
//     + time_rel (blocks 0..5)
__global__ void k0_init(const float* __restrict__ nfeat, int NN,
                        const int* __restrict__ dst, int E,
                        float* __restrict__ cat_hid,
                        const float* __restrict__ norm_emb,
                        const float* __restrict__ rel_emb,
                        const float* __restrict__ hour_emb,
                        const float* __restrict__ W,
                        const float* __restrict__ b) {
    int stride = gridDim.x * blockDim.x;
    int tid = blockIdx.x * blockDim.x + threadIdx.x;

    const float2* nf2 = (const float2*)nfeat;
    __half2* nh2 = (__half2*)g_nhalf;
    int n2 = NN * D / 2;
    for (int i = tid; i < n2; i += stride)
        nh2[i] = __float22half2_rn(nf2[i]);
    for (int e = tid; e < E; e += stride)
        atomicAdd(&g_cnt[dst[e]], 1);
    for (int i = tid; i < NC_NODES * D; i += stride)
        cat_hid[i] = 0.f;
    for (int i = tid; i < NC_NODES; i += stride)
        g_cdenom[i] = 0.f;
    // fp16 table conversions
    for (int i = tid; i < 7 * D; i += stride) {
        g_ntab[i] = __float2half_rn(norm_emb[i]);
        g_rtab[i] = __float2half_rn(rel_emb[i]);
    }

    if (blockIdx.x < HP) {
        __shared__ float mix[D];
        __shared__ float red[D];
        int h = blockIdx.x;
        int j = threadIdx.x;
        if (j < D) {
            int lh = (h - 1 + HP) % HP, nh = (h + 1) % HP;
            mix[j] = (hour_emb[lh * D + j] + hour_emb[h * D + j] + hour_emb[nh * D + j]) * (1.f / 3.f);
        }
        __syncthreads();
        float o = 0.f;
        if (j < D) {
            o = b[j];
            #pragma unroll
            for (int k = 0; k < D; k++) o = fmaf(W[j * D + k], mix[k], o);
            red[j] = o * o;
        }
        __syncthreads();
        #pragma unroll
        for (int s = 32; s > 0; s >>= 1) {
            if (j < s) red[j] += red[j + s];
            __syncthreads();
        }
        if (j < D) g_ttab[h * D + j] = __float2half_rn(o / fmaxf(sqrtf(red[0]), 1e-12f));
    }
}

// K2: per-block scan (1024 elements/block, 256 threads x 4)
__global__ void k2_scan_blocks(int NN) {
    __shared__ int sh[256];
    int b = blockIdx.x, t = threadIdx.x;
    int base = b * SCAN_BLK + t * 4;
    int v0 = (base + 0 < NN) ? g_cnt[base + 0] : 0;
    int v1 = (base + 1 < NN) ? g_cnt[base + 1] : 0;
    int v2 = (base + 2 < NN) ? g_cnt[base + 2] : 0;
    int v3 = (base + 3 < NN) ? g_cnt[base + 3] : 0;
    int s = v0 + v1 + v2 + v3;
    sh[t] = s;
    __syncthreads();
    #pragma unroll
    for (int off = 1; off < 256; off <<= 1) {
        int x = (t >= off) ? sh[t - off] : 0;
        __syncthreads();
        sh[t] += x;
        __syncthreads();
    }
    if (t == 255) g_bsum[b] = sh[255];
    int run = sh[t] - s;
    if (base + 0 < NN) g_off[base + 0] = run; run += v0;
    if (base + 1 < NN) g_off[base + 1] = run; run += v1;
    if (base + 2 < NN) g_off[base + 2] = run; run += v2;
    if (base + 3 < NN) g_off[base + 3] = run;
}

// K34: merged block-sum scan + finalize (+ g_cnt reset for next replay)
__global__ void k34_finalize(int NN, int E, int nblk) {
    __shared__ int sh[128];
    int t = threadIdx.x;   // 512
    if (t < 128) sh[t] = (t < nblk) ? g_bsum[t] : 0;
    __syncthreads();
    #pragma unroll
    for (int off = 1; off < 128; off <<= 1) {
        int x = (t >= off && t < 128) ? sh[t - off] : 0;
        __syncthreads();
        if (t < 128) sh[t] += x;
        __syncthreads();
    }
    int sb = (blockIdx.x * 512) >> 10;
    int bpre = (sb > 0) ? sh[sb - 1] : 0;
    int i = blockIdx.x * 512 + t;
    if (i < NN) {
        int v = g_off[i] + bpre;
        g_start[i] = v;
        g_cursor[i] = v;
        g_cnt[i] = 0;
    }
    if (i == 0) g_start[NN] = E;
}

// ---------------------------------------------------------------------------
// K6: pass-1 scores, 8 lanes per edge, 4 edges per warp, fused CSR scatter.
// fp16 rows AND fp16 tables: 6 x LDG.128 per lane (was 10).
__global__ void __launch_bounds__(256) k6_pass1(
        const float* __restrict__ cat_emb,
        const float* __restrict__ rel_emb,
        const int* __restrict__ src,
        const int* __restrict__ dst,
        const int* __restrict__ ftype,
        const int* __restrict__ hourid,
        const int* __restrict__ csrc,
        const int* __restrict__ cdst,
        int E, int EC, int warps_cat, int n_warps) {
    int w = (blockIdx.x * blockDim.x + threadIdx.x) >> 5;
    int lane = threadIdx.x & 31;
    if (w >= n_warps) return;
    int grp = lane >> 3;       // 0..3
    int l   = lane & 7;        // 0..7

    if (w < warps_cat) {
        int e = 4 * w + grp;
        bool valid = (e < EC);
        int ec = valid ? e : EC - 1;
        int s = csrc[ec], d = cdst[ec];
        const float4* ce4 = (const float4*)cat_emb;
        const float4* re4 = (const float4*)rel_emb;
        float ssq = 0.f;
        #pragma unroll
        for (int q = 0; q < 2; q++) {
            float4 hc = ce4[s * 16 + 2 * l + q];
            float4 tc = ce4[d * 16 + 2 * l + q];
            float4 rc = re4[6 * 16 + 2 * l + q];
            float dx = hc.x + rc.x - tc.x;
            float dy = hc.y + rc.y - tc.y;
            float dz = hc.z + rc.z - tc.z;
            float dw = hc.w + rc.w - tc.w;
            ssq += fmaf(dx, dx, fmaf(dy, dy, fmaf(dz, dz, dw * dw)));
        }
        ssq = sum8(ssq);
        if (l == 0 && valid) {
            float wgt = __expf(__expf(-ssq));
            g_cw[e] = wgt;
            atomicAdd(&g_cdenom[d], wgt);
        }
    } else {
        int e = 4 * (w - warps_cat) + grp;
        bool valid = (e < E);
        int ec = valid ? e : E - 1;
        int s = src[ec], d = dst[ec], f = ftype[ec], h = hourid[ec];

        const float4* nh4 = (const float4*)g_nhalf;   // 8 halfs per float4, 8 float4/row
        const float4* nt4 = (const float4*)g_ntab;    // 8 float4 per row
        const float4* rt4 = (const float4*)g_rtab;
        const float4* tt4 = (const float4*)g_ttab;

        float a[8], bb[8], u[8], n[8], tn[8], r[8], tr[8];
        unpack8(nh4[s * 8 + l], a);
        unpack8(nh4[d * 8 + l], bb);
        unpack8(nt4[f * 8 + l], n);
        unpack8(nt4[5 * 8 + l], tn);
        unpack8(rt4[f * 8 + l], r);
        unpack8(tt4[h * 8 + l], tr);

        #pragma unroll
        for (int i = 0; i < 8; i++) u[i] = a[i] - bb[i];

        float p1 = 0.f, p2 = 0.f;
        #pragma unroll
        for (int i = 0; i < 8; i++) {
            p1 = fmaf(u[i], n[i], p1);
            p2 = fmaf(u[i], tn[i], p2);
        }
        float dot1 = sum8(p1);
        float dot2 = sum8(p2);

        float ssq = 0.f;
        #pragma unroll
        for (int i = 0; i < 8; i++) {
            float d1 = u[i] - dot1 * n[i] + r[i];
            float d2 = u[i] - dot2 * tn[i] + tr[i];
            ssq = fmaf(d1, d1, fmaf(d2, d2, ssq));
        }
        ssq = sum8(ssq);

        if (l == 0 && valid) {
            float wgt = __expf(__expf(-ssq));
            int pos = atomicAdd(&g_cursor[d], 1);
            g_slot_src[pos] = s;
            g_wslot[pos] = wgt;
        }
    }
}

// ---------------------------------------------------------------------------
// K7: warps < ECH: cat pass2 (REDG into zeroed cat_hid). Others: 2 nodes/warp gather.
__global__ void k7_aggregate(const float* __restrict__ cat_emb,
                             const int* __restrict__ csrc,
                             const int* __restrict__ cdst,
                             float* __restrict__ rst,
                             float* __restrict__ cat_hid,
                             int NN, int EC, int ECH, int n_warps) {
    int w = (blockIdx.x * blockDim.x + threadIdx.x) >> 5;
    int lane = threadIdx.x & 31;
    if (w >= n_warps) return;
    int half = lane >> 4;
    int l = lane & 15;

    if (w < ECH) {
        int e = 2 * w + half;
        if (e >= EC) return;
        int s = csrc[e], d = cdst[e];
        float coeff = g_cw[e] / g_cdenom[d];
        float4 v = ((const float4*)cat_emb)[s * 16 + l];
        red_add_v4(&cat_hid[d * D + l * 4],
                   v.x * coeff, v.y * coeff, v.z * coeff, v.w * coeff);
    } else {
        int node = 2 * (w - ECH) + half;
        if (node >= NN) return;
        int st = g_start[node], en = g_start[node + 1];
        float4 acc = make_float4(0.f, 0.f, 0.f, 0.f);
        if (en > st) {
            float denom = 0.f;
            for (int j = st + l; j < en; j += 16) denom += g_wslot[j];
            denom = half_sum(denom);
            float inv = 1.f / denom;
            const float2* nh2 = (const float2*)g_nhalf;
            for (int j = st; j < en; j++) {
                float cw = g_wslot[j] * inv;
                int s = g_slot_src[j];
                float2 rv = nh2[s * 16 + l];
                __half2* pv = (__half2*)&rv;
                float2 v0 = __half22float2(pv[0]), v1 = __half22float2(pv[1]);
                acc.x = fmaf(cw, v0.x, acc.x);
                acc.y = fmaf(cw, v0.y, acc.y);
                acc.z = fmaf(cw, v1.x, acc.z);
                acc.w = fmaf(cw, v1.y, acc.w);
            }
        }
        ((float4*)rst)[node * 16 + l] = acc;
    }
}

// ---------------------------------------------------------------------------
extern "C" void kernel_launch(void* const* d_in, const int* in_sizes, int n_in,
                              void* d_out, int out_size) {
    const float* nfeat      = (const float*)d_in[0];
    const float* cat_emb    = (const float*)d_in[1];
    const float* rel_emb    = (const float*)d_in[2];
    const float* norm_emb   = (const float*)d_in[3];
    const float* hour_emb   = (const float*)d_in[4];
    const float* time_rel_w = (const float*)d_in[5];
    const float* time_rel_b = (const float*)d_in[6];
    const int*   src        = (const int*)d_in[7];
    const int*   dst        = (const int*)d_in[8];
    const int*   ftype      = (const int*)d_in[9];
    const int*   hourid     = (const int*)d_in[10];
    const int*   cat_src    = (const int*)d_in[11];
    const int*   cat_dst    = (const int*)d_in[12];

    const int NN = in_sizes[0] / D;
    const int E  = in_sizes[7];
    const int EC = in_sizes[11];

    float* out     = (float*)d_out;
    float* rst     = out;
    float* cat_hid = out + NN * D;

    // K0: conversions + histogram + zeros + time_rel
    k0_init<<<2048, 256>>>(nfeat, NN, dst, E, cat_hid, norm_emb, rel_emb,
                           hour_emb, time_rel_w, time_rel_b);

    // CSR row pointers (scatter fused into pass1)
    int nblk = (NN + SCAN_BLK - 1) / SCAN_BLK;
    k2_scan_blocks<<<nblk, 256>>>(NN);
    k34_finalize<<<(NN + 511) / 512, 512>>>(NN, E, nblk);

    // Pass 1 (scores + fused scatter)
    {
        int warps_cat = (EC + 3) / 4;
        int n_warps = warps_cat + (E + 3) / 4;
        int blocks = (n_warps * 32 + 255) / 256;
        k6_pass1<<<blocks, 256>>>(cat_emb, rel_emb,
                                  src, dst, ftype, hourid, cat_src, cat_dst,
                                  E, EC, warps_cat, n_warps);
    }

    // Pass 2 (aggregate)
    {
        int ECH = (EC + 1) / 2;
        int n_warps = ECH + (NN + 1) / 2;
        int blocks = (n_warps * 32 + 255) / 256;
        k7_aggregate<<<blocks, 256>>>(cat_emb, cat_src, cat_dst,
                                      rst, cat_hid, NN, EC, ECH, n_warps);
    }
}